// round 6
// baseline (speedup 1.0000x reference)
#include <cuda_runtime.h>
#include <cuda_bf16.h>
#include <cstdint>

// Problem constants
#define NN    20000
#define EE    320000
#define NPAD  20032        // 313 * 64
#define OUTW  208          // 16 + 3*64

// ---------------- scratch (device globals; no allocation) ----------------
__device__ float g_feat[NPAD * 64];          // current node features (padded rows stay 0)
__device__ float g_cat[NPAD * 768];          // [f_ni | f_nj | hn] per node
__device__ float g_elog[EE * 4];             // per-edge per-head logits
__device__ float g_agg[NPAD * 256];          // aggregated messages (N,H*D)
__device__ int   g_off[NN + 1];              // CSR offsets by dst
__device__ int   g_cursor[NN];               // deg counter, then scatter cursor
__device__ int   g_perm[EE];                 // edge ids sorted by dst

// ---------------- CSR build ----------------
__global__ void k_zero_cursor() {
    int i = blockIdx.x * blockDim.x + threadIdx.x;
    if (i < NN) g_cursor[i] = 0;
}

__global__ void k_degree(const int* __restrict__ dst) {
    int e = blockIdx.x * blockDim.x + threadIdx.x;
    if (e < EE) atomicAdd(&g_cursor[dst[e]], 1);
}

__global__ void k_scan() {
    __shared__ int s[1024];
    __shared__ int carry;
    int t = threadIdx.x;
    if (t == 0) { carry = 0; g_off[0] = 0; }
    __syncthreads();
    for (int base = 0; base < NN; base += 1024) {
        int x = (base + t < NN) ? g_cursor[base + t] : 0;
        s[t] = x;
        __syncthreads();
        for (int d = 1; d < 1024; d <<= 1) {
            int v = (t >= d) ? s[t - d] : 0;
            __syncthreads();
            s[t] += v;
            __syncthreads();
        }
        if (base + t < NN) g_off[base + t + 1] = carry + s[t];
        __syncthreads();
        if (t == 0) carry += s[1023];
        __syncthreads();
    }
}

__global__ void k_copy_cursor() {
    int i = blockIdx.x * blockDim.x + threadIdx.x;
    if (i < NN) g_cursor[i] = g_off[i];
}

__global__ void k_scatter(const int* __restrict__ dst) {
    int e = blockIdx.x * blockDim.x + threadIdx.x;
    if (e < EE) {
        int p = atomicAdd(&g_cursor[dst[e]], 1);
        g_perm[p] = e;
    }
}

// ---------------- output col 0..15: raw node features ----------------
__global__ void k_copy_nf(const float* __restrict__ nf, float* __restrict__ out) {
    int i = blockIdx.x * blockDim.x + threadIdx.x;   // over NN*16
    if (i < NN * 16) {
        int n = i >> 4, k = i & 15;
        out[n * OUTW + k] = nf[i];
    }
}

// ---------------- embed: feat = nf @ W_embed + b ----------------
__global__ void k_embed(const float* __restrict__ nf,
                        const float* __restrict__ W,    // 16x64
                        const float* __restrict__ b,    // 64
                        float* __restrict__ out) {
    __shared__ float sW[16 * 64];
    int tid = threadIdx.x;
#pragma unroll
    for (int i = 0; i < 4; i++) sW[tid + i * 256] = W[tid + i * 256];
    __syncthreads();
    int n = blockIdx.x * 4 + (tid >> 6);
    int c = tid & 63;
    if (n < NN) {
        float acc = b[c];
        const float* r = nf + n * 16;
#pragma unroll
        for (int k = 0; k < 16; k++) acc += r[k] * sW[k * 64 + c];
        g_feat[n * 64 + c] = acc;
        out[n * OUTW + 16 + c] = acc;
    }
}

// ---------------- node GEMM: g_cat = g_feat @ [W_ni | W_nj | W_node] ----------------
// Block: 64 rows x 256 cols, 256 threads, 8x8 per thread, cols strided by 32.
__global__ __launch_bounds__(256) void k_nodegemm(
    const float* __restrict__ Wni, const float* __restrict__ Wnj,
    const float* __restrict__ Wnode) {
    __shared__ float sA[64][17];
    __shared__ float sB[16][256];
    int tid = threadIdx.x;
    int tr = tid >> 5;            // 0..7
    int tc = tid & 31;            // 0..31
    int row0 = blockIdx.x * 64;
    int nb = blockIdx.y;          // 0: ni, 1: nj, 2: node
    const float* B = (nb == 0) ? Wni : (nb == 1) ? Wnj : Wnode;

    float acc[8][8];
#pragma unroll
    for (int i = 0; i < 8; i++)
#pragma unroll
        for (int j = 0; j < 8; j++) acc[i][j] = 0.f;

    for (int k0 = 0; k0 < 64; k0 += 16) {
        __syncthreads();
#pragma unroll
        for (int i = 0; i < 16; i++) {
            int idx = tid + i * 256;
            sB[idx >> 8][idx & 255] = B[(k0 + (idx >> 8)) * 256 + (idx & 255)];
        }
        {
            int er = tid >> 2;
            int cc = (tid & 3) * 4;
            float4 v = *reinterpret_cast<const float4*>(
                &g_feat[(row0 + er) * 64 + k0 + cc]);
            sA[er][cc + 0] = v.x; sA[er][cc + 1] = v.y;
            sA[er][cc + 2] = v.z; sA[er][cc + 3] = v.w;
        }
        __syncthreads();
#pragma unroll
        for (int kk = 0; kk < 16; kk++) {
            float a[8], bb[8];
#pragma unroll
            for (int i = 0; i < 8; i++) a[i] = sA[tr * 8 + i][kk];
#pragma unroll
            for (int j = 0; j < 8; j++) bb[j] = sB[kk][tc + j * 32];
#pragma unroll
            for (int i = 0; i < 8; i++)
#pragma unroll
                for (int j = 0; j < 8; j++) acc[i][j] += a[i] * bb[j];
        }
    }
#pragma unroll
    for (int i = 0; i < 8; i++) {
        int r = row0 + tr * 8 + i;
        float* C = g_cat + r * 768 + nb * 256;
#pragma unroll
        for (int j = 0; j < 8; j++) C[tc + j * 32] = acc[i][j];
    }
}

// ---------------- fused edge logits ----------------
// per block: 64 edges. GEMM edge_feat(64x64) @ W_fij(64x256) fused with gathers,
// bias, leaky_relu, per-head attn dot, warp-reduce -> g_elog (E x 4).
__global__ __launch_bounds__(256) void k_edge_logits(
    const float* __restrict__ edge_feat,   // E x 64
    const float* __restrict__ Wf,          // 64 x 256 (layer slice)
    const float* __restrict__ batt,        // 256
    const float* __restrict__ attn,        // 256
    const int* __restrict__ src, const int* __restrict__ dst) {
    __shared__ float sA[64][17];
    __shared__ float sB[16][256];
    __shared__ float sb[256], sat[256];
    __shared__ int ssrc[64], sdst[64];
    int tid = threadIdx.x;
    int tr = tid >> 5;
    int tc = tid & 31;
    int e0 = blockIdx.x * 64;

    sb[tid]  = batt[tid];
    sat[tid] = attn[tid];
    if (tid < 64) { ssrc[tid] = src[e0 + tid]; sdst[tid] = dst[e0 + tid]; }

    float acc[8][8];
#pragma unroll
    for (int i = 0; i < 8; i++)
#pragma unroll
        for (int j = 0; j < 8; j++) acc[i][j] = 0.f;

    for (int k0 = 0; k0 < 64; k0 += 16) {
        __syncthreads();
#pragma unroll
        for (int i = 0; i < 16; i++) {
            int idx = tid + i * 256;
            sB[idx >> 8][idx & 255] = Wf[(k0 + (idx >> 8)) * 256 + (idx & 255)];
        }
        {
            int er = tid >> 2;
            int cc = (tid & 3) * 4;
            float4 v = *reinterpret_cast<const float4*>(
                &edge_feat[(size_t)(e0 + er) * 64 + k0 + cc]);
            sA[er][cc + 0] = v.x; sA[er][cc + 1] = v.y;
            sA[er][cc + 2] = v.z; sA[er][cc + 3] = v.w;
        }
        __syncthreads();
#pragma unroll
        for (int kk = 0; kk < 16; kk++) {
            float a[8], bb[8];
#pragma unroll
            for (int i = 0; i < 8; i++) a[i] = sA[tr * 8 + i][kk];
#pragma unroll
            for (int j = 0; j < 8; j++) bb[j] = sB[kk][tc + j * 32];
#pragma unroll
            for (int i = 0; i < 8; i++)
#pragma unroll
                for (int j = 0; j < 8; j++) acc[i][j] += a[i] * bb[j];
        }
    }

    // epilogue: gather + bias + leaky + attn dot + warp reduce
#pragma unroll
    for (int i = 0; i < 8; i++) {
        int el = tr * 8 + i;
        int s = ssrc[el], d = sdst[el];
        const float* pni = g_cat + s * 768;          // f_ni row
        const float* pnj = g_cat + d * 768 + 256;    // f_nj row
        float part[4] = {0.f, 0.f, 0.f, 0.f};
#pragma unroll
        for (int j = 0; j < 8; j++) {
            int c = tc + j * 32;                      // head = j>>1 (uniform)
            float x = acc[i][j] + pni[c] + pnj[c] + sb[c];
            x = (x > 0.f) ? x : 0.2f * x;
            part[j >> 1] += x * sat[c];
        }
#pragma unroll
        for (int o = 16; o; o >>= 1) {
#pragma unroll
            for (int h = 0; h < 4; h++)
                part[h] += __shfl_xor_sync(0xffffffffu, part[h], o);
        }
        if (tc == 0) {
            float4 v = make_float4(part[0], part[1], part[2], part[3]);
            *reinterpret_cast<float4*>(&g_elog[(size_t)(e0 + el) * 4]) = v;
        }
    }
}

// ---------------- softmax + aggregation: warp per dst node (CSR) ----------------
__global__ __launch_bounds__(256) void k_aggregate(const int* __restrict__ src) {
    __shared__ float sw[8][32][4];
    __shared__ int   se[8][32];
    int tid = threadIdx.x;
    int w = tid >> 5;
    int lane = tid & 31;
    int node = blockIdx.x * 8 + w;
    if (node >= NN) return;
    int lo = g_off[node], hi = g_off[node + 1];

    const float4* elog4 = reinterpret_cast<const float4*>(g_elog);

    // pass 1: per-head max
    float4 mx = make_float4(-1e30f, -1e30f, -1e30f, -1e30f);
    for (int i = lo + lane; i < hi; i += 32) {
        float4 v = elog4[g_perm[i]];
        mx.x = fmaxf(mx.x, v.x); mx.y = fmaxf(mx.y, v.y);
        mx.z = fmaxf(mx.z, v.z); mx.w = fmaxf(mx.w, v.w);
    }
#pragma unroll
    for (int o = 16; o; o >>= 1) {
        mx.x = fmaxf(mx.x, __shfl_xor_sync(0xffffffffu, mx.x, o));
        mx.y = fmaxf(mx.y, __shfl_xor_sync(0xffffffffu, mx.y, o));
        mx.z = fmaxf(mx.z, __shfl_xor_sync(0xffffffffu, mx.z, o));
        mx.w = fmaxf(mx.w, __shfl_xor_sync(0xffffffffu, mx.w, o));
    }

    // pass 2: per-head sum of exp
    float4 z = make_float4(0.f, 0.f, 0.f, 0.f);
    for (int i = lo + lane; i < hi; i += 32) {
        float4 v = elog4[g_perm[i]];
        z.x += __expf(v.x - mx.x); z.y += __expf(v.y - mx.y);
        z.z += __expf(v.z - mx.z); z.w += __expf(v.w - mx.w);
    }
#pragma unroll
    for (int o = 16; o; o >>= 1) {
        z.x += __shfl_xor_sync(0xffffffffu, z.x, o);
        z.y += __shfl_xor_sync(0xffffffffu, z.y, o);
        z.z += __shfl_xor_sync(0xffffffffu, z.z, o);
        z.w += __shfl_xor_sync(0xffffffffu, z.w, o);
    }
    float4 zi;
    zi.x = (z.x > 0.f) ? 1.f / z.x : 0.f;
    zi.y = (z.y > 0.f) ? 1.f / z.y : 0.f;
    zi.z = (z.z > 0.f) ? 1.f / z.z : 0.f;
    zi.w = (z.w > 0.f) ? 1.f / z.w : 0.f;

    // pass 3: weighted aggregation of hn[src]; weights computed once/edge (chunked)
    float acc[8];
#pragma unroll
    for (int j = 0; j < 8; j++) acc[j] = 0.f;

    for (int c0 = lo; c0 < hi; c0 += 32) {
        int i = c0 + lane;
        if (i < hi) {
            int e = g_perm[i];
            float4 v = elog4[e];
            sw[w][lane][0] = __expf(v.x - mx.x) * zi.x;
            sw[w][lane][1] = __expf(v.y - mx.y) * zi.y;
            sw[w][lane][2] = __expf(v.z - mx.z) * zi.z;
            sw[w][lane][3] = __expf(v.w - mx.w) * zi.w;
            se[w][lane] = src[e];
        }
        __syncwarp();
        int cnt = min(32, hi - c0);
        for (int u = 0; u < cnt; u++) {
            float w0 = sw[w][u][0], w1 = sw[w][u][1];
            float w2 = sw[w][u][2], w3 = sw[w][u][3];
            const float* hrow = g_cat + se[w][u] * 768 + 512;   // hn row
            acc[0] += hrow[lane]       * w0;
            acc[1] += hrow[32 + lane]  * w0;
            acc[2] += hrow[64 + lane]  * w1;
            acc[3] += hrow[96 + lane]  * w1;
            acc[4] += hrow[128 + lane] * w2;
            acc[5] += hrow[160 + lane] * w2;
            acc[6] += hrow[192 + lane] * w3;
            acc[7] += hrow[224 + lane] * w3;
        }
        __syncwarp();
    }
#pragma unroll
    for (int j = 0; j < 8; j++) g_agg[node * 256 + j * 32 + lane] = acc[j];
}

// ---------------- MLP + residual: feat = g_agg @ W_mlp + b + feat ----------------
// Block: 64 rows x 64 cols, 256 threads, 8 rows x 2 cols (strided 32) per thread.
__global__ __launch_bounds__(256) void k_mlp(
    const float* __restrict__ Wm,    // 256 x 64 (layer slice)
    const float* __restrict__ bm,    // 64
    float* __restrict__ out, int outbase) {
    __shared__ float sA[64][33];
    __shared__ float sB[32][64];
    int tid = threadIdx.x;
    int tr = tid >> 5;
    int tc = tid & 31;
    int row0 = blockIdx.x * 64;

    float acc[8][2];
#pragma unroll
    for (int i = 0; i < 8; i++) { acc[i][0] = 0.f; acc[i][1] = 0.f; }

    for (int k0 = 0; k0 < 256; k0 += 32) {
        __syncthreads();
        {
            int er = tid >> 2;
            int cc = (tid & 3) * 8;
            float4 v0 = *reinterpret_cast<const float4*>(
                &g_agg[(row0 + er) * 256 + k0 + cc]);
            float4 v1 = *reinterpret_cast<const float4*>(
                &g_agg[(row0 + er) * 256 + k0 + cc + 4]);
            sA[er][cc + 0] = v0.x; sA[er][cc + 1] = v0.y; sA[er][cc + 2] = v0.z; sA[er][cc + 3] = v0.w;
            sA[er][cc + 4] = v1.x; sA[er][cc + 5] = v1.y; sA[er][cc + 6] = v1.z; sA[er][cc + 7] = v1.w;
        }
#pragma unroll
        for (int i = 0; i < 8; i++) {
            int idx = tid + i * 256;
            sB[idx >> 6][idx & 63] = Wm[(k0 + (idx >> 6)) * 64 + (idx & 63)];
        }
        __syncthreads();
#pragma unroll
        for (int kk = 0; kk < 32; kk++) {
            float a[8];
#pragma unroll
            for (int i = 0; i < 8; i++) a[i] = sA[tr * 8 + i][kk];
            float b0 = sB[kk][tc], b1 = sB[kk][tc + 32];
#pragma unroll
            for (int i = 0; i < 8; i++) { acc[i][0] += a[i] * b0; acc[i][1] += a[i] * b1; }
        }
    }
#pragma unroll
    for (int i = 0; i < 8; i++) {
        int r = row0 + tr * 8 + i;
        if (r < NN) {
#pragma unroll
            for (int jj = 0; jj < 2; jj++) {
                int c = tc + jj * 32;
                float v = acc[i][jj] + bm[c] + g_feat[r * 64 + c];
                g_feat[r * 64 + c] = v;
                out[r * OUTW + outbase + c] = v;
            }
        }
    }
}

// ---------------- launch ----------------
extern "C" void kernel_launch(void* const* d_in, const int* in_sizes, int n_in,
                              void* d_out, int out_size) {
    const float* node_feat = (const float*)d_in[0];
    const float* edge_feat = (const float*)d_in[1];
    const int*   src       = (const int*)d_in[2];
    const int*   dst       = (const int*)d_in[3];
    const float* W_embed   = (const float*)d_in[4];
    const float* b_embed   = (const float*)d_in[5];
    const float* W_ni      = (const float*)d_in[6];
    const float* W_nj      = (const float*)d_in[7];
    const float* W_fij     = (const float*)d_in[8];
    const float* b_att     = (const float*)d_in[9];
    const float* attn      = (const float*)d_in[10];
    const float* W_node    = (const float*)d_in[11];
    const float* W_mlp     = (const float*)d_in[12];
    const float* b_mlp     = (const float*)d_in[13];
    float* out = (float*)d_out;

    // CSR by dst (depends only on dst; rebuilt every call)
    k_zero_cursor<<<(NN + 255) / 256, 256>>>();
    k_degree<<<(EE + 255) / 256, 256>>>(dst);
    k_scan<<<1, 1024>>>();
    k_copy_cursor<<<(NN + 255) / 256, 256>>>();
    k_scatter<<<(EE + 255) / 256, 256>>>(dst);

    // output cols 0..15 + embed (cols 16..79)
    k_copy_nf<<<(NN * 16 + 255) / 256, 256>>>(node_feat, out);
    k_embed<<<NN / 4, 256>>>(node_feat, W_embed, b_embed, out);

    for (int L = 0; L < 2; L++) {
        const float* Wni  = W_ni   + L * 64 * 256;
        const float* Wnj  = W_nj   + L * 64 * 256;
        const float* Wfij = W_fij  + L * 64 * 256;
        const float* ba   = b_att  + L * 256;
        const float* at   = attn   + L * 256;
        const float* Wnd  = W_node + L * 64 * 256;
        const float* Wm   = W_mlp  + L * 256 * 64;
        const float* bm   = b_mlp  + L * 64;

        dim3 ng(NPAD / 64, 3);
        k_nodegemm<<<ng, 256>>>(Wni, Wnj, Wnd);
        k_edge_logits<<<EE / 64, 256>>>(edge_feat, Wfij, ba, at, src, dst);
        k_aggregate<<<NN / 8, 256>>>(src);
        k_mlp<<<NPAD / 64, 256>>>(Wm, bm, out, 80 + 64 * L);
    }
}